// round 11
// baseline (speedup 1.0000x reference)
#include <cuda_runtime.h>

typedef unsigned long long u64;

#define NT 256
#define BT 32
#define RSTR 36          /* float row stride: 144B, 16B-aligned for every k */
#define B_TOT 8192
#define T_STEPS 30
#define WARM 24
#define WCH 8192         /* floats per staging chunk (32KB) */

__device__ __forceinline__ u64 pack2(float lo, float hi){
    u64 r; asm("mov.b64 %0, {%1, %2};" : "=l"(r) : "f"(lo), "f"(hi)); return r;
}
__device__ __forceinline__ void unpack2(u64 v, float& lo, float& hi){
    asm("mov.b64 {%0, %1}, %2;" : "=f"(lo), "=f"(hi) : "l"(v));
}
__device__ __forceinline__ u64 fma2(u64 a, u64 b, u64 c){
    u64 d; asm("fma.rn.f32x2 %0, %1, %2, %3;" : "=l"(d) : "l"(a), "l"(b), "l"(c)); return d;
}
__device__ __forceinline__ float sig_(float x){ return __fdividef(1.f, 1.f + __expf(-x)); }
__device__ __forceinline__ float tanh_(float x){ return 1.f - 2.f * __fdividef(1.f, __expf(2.f * x) + 1.f); }

#define CPA16(dst_u32, src) asm volatile("cp.async.cg.shared.global [%0], [%1], 16;" :: "r"(dst_u32), "l"(src))
#define CPA_COMMIT() asm volatile("cp.async.commit_group;")
#define CPA_WAIT()   asm volatile("cp.async.wait_group 0;")

__device__ __forceinline__ void stage(float* dst, const float* __restrict__ src, int nfloats, int tid){
    unsigned d = (unsigned)__cvta_generic_to_shared(dst);
    for (int i = tid; i < (nfloats >> 2); i += NT)
        CPA16(d + i * 16, src + i * 4);
    CPA_COMMIT();
}

// smem floats/block: wsm 2*8192 | hbuf 136*36 | m1buf 128*36 | red 64 | predb 32  (~101.7KB, 2 blocks fit)
#define SMEM_FLOATS (2*WCH + 136*RSTR + 128*RSTR + 2*BT + BT)
#define SMEM_BYTES (SMEM_FLOATS * 4)

__global__ void __launch_bounds__(NT, 2)
fused_lstm_kernel(const float* __restrict__ x0, const float* __restrict__ x1,
                  const float* __restrict__ x2, const float* __restrict__ x3,
                  const float* __restrict__ x4, const float* __restrict__ x5,
                  const float* __restrict__ x6, const float* __restrict__ irr,
                  const float* __restrict__ Wi, const float* __restrict__ Wh,
                  const float* __restrict__ bz, const float* __restrict__ W1,
                  const float* __restrict__ b1, const float* __restrict__ W2,
                  const float* __restrict__ b2, const float* __restrict__ Wout,
                  const float* __restrict__ bout, float* __restrict__ out)
{
    extern __shared__ float smem[];
    float* wsm   = smem;                  // 2 x 8192 weight staging (16B aligned)
    float* hbuf  = wsm   + 2 * WCH;       // [136][36]: rows 0-127 h, 128-135 inputs
    float* m1buf = hbuf  + 136 * RSTR;    // [128][36]
    float* red   = m1buf + 128 * RSTR;    // [2][32]
    float* predb = red   + 2 * BT;        // [32]

    const int tid = threadIdx.x;
    const int rg  = tid >> 6;             // 0..3, 8 batch rows each
    const int cg  = tid & 63;             // 0..63, 2 channels each
    const int r0  = rg << 3;
    const int ch0 = cg << 1;
    const int b0  = blockIdx.x * BT;

    // ---- constants to registers ----
    u64 bzr[4];
    #pragma unroll
    for (int q = 0; q < 4; q++) bzr[q] = *reinterpret_cast<const u64*>(&bz[(q << 7) + ch0]);
    const u64 cb1r = *reinterpret_cast<const u64*>(&b1[ch0]);
    const u64 cb2r = *reinterpret_cast<const u64*>(&b2[ch0]);
    const float wo0 = Wout[ch0], wo1 = Wout[ch0 + 1];
    const float boutv = bout[0];

    // ---- input feature pointers: 8 feats x 32 rows == all 256 threads ----
    const int lf = tid >> 5, lr = tid & 31;
    const float* fptr;
    if      (lf == 0) fptr = x0; else if (lf == 1) fptr = x1;
    else if (lf == 2) fptr = x2; else if (lf == 3) fptr = x3;
    else if (lf == 4) fptr = x4; else if (lf == 5) fptr = x5;
    else if (lf == 6) fptr = x6; else              fptr = irr;
    {
        int lb = b0 + lr;
        fptr = (lf < 7) ? (fptr + lb * T_STEPS) : (fptr + lb * WARM);
    }
    const int tmax = (lf < 7) ? (T_STEPS - 1) : (WARM - 1);
    float vin = __ldg(fptr);

    // ---- init h = 0 ----
    for (int i = tid; i < 128 * RSTR; i += NT) hbuf[i] = 0.f;

    // ---- prologue: stage Wh rows 0-15 into wsm[0] ----
    stage(wsm, Wh, WCH, tid);
    CPA_WAIT();
    int pb = 0;

    u64 cst[4][2];
    #pragma unroll
    for (int rp = 0; rp < 4; rp++){ cst[rp][0] = 0ull; cst[rp][1] = 0ull; }

    __syncthreads();

    for (int t = 0; t < T_STEPS; ++t){
        // ---- stage this step's input; prefetch next ----
        {
            float v = (lf < 7 || t < WARM) ? vin : predb[lr];
            hbuf[(128 + lf) * RSTR + lr] = v;
            int tn = (t + 1 < tmax) ? (t + 1) : tmax;
            vin = __ldg(fptr + tn);
        }

        // ================= z = [h, inp] @ [Wh; Wi] + b =================
        u64 acc[4][8];
        #pragma unroll
        for (int q = 0; q < 4; q++){
            float bq0, bq1; unpack2(bzr[q], bq0, bq1);
            u64 p0 = pack2(bq0, bq0), p1 = pack2(bq1, bq1);
            #pragma unroll
            for (int rp = 0; rp < 4; rp++){ acc[rp][(q<<1)] = p0; acc[rp][(q<<1)+1] = p1; }
        }

        // 9 chunks: c0..7 = Wh rows 16c..16c+15, c8 = Wi (8 rows)
        for (int c = 0; c <= 8; ++c){
            if (c < 7)       stage(wsm + ((pb ^ 1) << 13), Wh + (c + 1) * WCH, WCH, tid);
            else if (c == 7) stage(wsm + ((pb ^ 1) << 13), Wi, 4096, tid);
            else             stage(wsm + ((pb ^ 1) << 13), W1, WCH, tid);

            const float* wb = wsm + (pb << 13);
            const int nk = (c < 8) ? 16 : 8;
            const int k0 = c << 4;
            #pragma unroll 8
            for (int kk = 0; kk < nk; kk++){
                const u64* h64 = reinterpret_cast<const u64*>(hbuf + (k0 + kk) * RSTR + r0);
                ulonglong2 ha = *reinterpret_cast<const ulonglong2*>(h64);      // 16B aligned
                ulonglong2 hb = *reinterpret_cast<const ulonglong2*>(h64 + 2);
                u64 hp0 = ha.x, hp1 = ha.y, hp2 = hb.x, hp3 = hb.y;
                #pragma unroll
                for (int q = 0; q < 4; q++){
                    u64 wp = *reinterpret_cast<const u64*>(&wb[(kk << 9) + (q << 7) + ch0]);
                    float w0, w1; unpack2(wp, w0, w1);
                    u64 w00 = pack2(w0, w0), w11 = pack2(w1, w1);
                    acc[0][(q<<1)]   = fma2(hp0, w00, acc[0][(q<<1)]);
                    acc[1][(q<<1)]   = fma2(hp1, w00, acc[1][(q<<1)]);
                    acc[2][(q<<1)]   = fma2(hp2, w00, acc[2][(q<<1)]);
                    acc[3][(q<<1)]   = fma2(hp3, w00, acc[3][(q<<1)]);
                    acc[0][(q<<1)+1] = fma2(hp0, w11, acc[0][(q<<1)+1]);
                    acc[1][(q<<1)+1] = fma2(hp1, w11, acc[1][(q<<1)+1]);
                    acc[2][(q<<1)+1] = fma2(hp2, w11, acc[2][(q<<1)+1]);
                    acc[3][(q<<1)+1] = fma2(hp3, w11, acc[3][(q<<1)+1]);
                }
            }
            CPA_WAIT();
            __syncthreads();
            pb ^= 1;
        }

        // ================= gates; c-state in regs; write new h =================
        #pragma unroll
        for (int rp = 0; rp < 4; rp++)
            #pragma unroll
            for (int d = 0; d < 2; d++){
                float zi0,zi1,zf0,zf1,zg0,zg1,zo0,zo1,c0,c1;
                unpack2(acc[rp][0+d], zi0, zi1);
                unpack2(acc[rp][2+d], zf0, zf1);
                unpack2(acc[rp][4+d], zg0, zg1);
                unpack2(acc[rp][6+d], zo0, zo1);
                unpack2(cst[rp][d], c0, c1);
                c0 = sig_(zf0)*c0 + sig_(zi0)*tanh_(zg0);
                c1 = sig_(zf1)*c1 + sig_(zi1)*tanh_(zg1);
                cst[rp][d] = pack2(c0, c1);
                float h0 = sig_(zo0)*tanh_(c0);
                float h1 = sig_(zo1)*tanh_(c1);
                *reinterpret_cast<u64*>(&hbuf[(ch0+d)*RSTR + r0 + (rp<<1)]) = pack2(h0, h1);
            }
        __syncthreads();

        // ================= m1 = relu(h @ W1 + b1): 2 chunks x 64 rows =================
        u64 a1[4][2];
        {
            float q0, q1; unpack2(cb1r, q0, q1);
            u64 p0 = pack2(q0,q0), p1 = pack2(q1,q1);
            #pragma unroll
            for (int rp = 0; rp < 4; rp++){ a1[rp][0] = p0; a1[rp][1] = p1; }
        }
        for (int c = 0; c < 2; ++c){
            if (c == 0) stage(wsm + ((pb ^ 1) << 13), W1 + WCH, WCH, tid);
            else        stage(wsm + ((pb ^ 1) << 13), W2, WCH, tid);

            const float* wb = wsm + (pb << 13);
            const int k0 = c << 6;
            #pragma unroll 8
            for (int kk = 0; kk < 64; kk++){
                const u64* h64 = reinterpret_cast<const u64*>(hbuf + (k0 + kk) * RSTR + r0);
                ulonglong2 ha = *reinterpret_cast<const ulonglong2*>(h64);
                ulonglong2 hb = *reinterpret_cast<const ulonglong2*>(h64 + 2);
                u64 hp0 = ha.x, hp1 = ha.y, hp2 = hb.x, hp3 = hb.y;
                u64 wp = *reinterpret_cast<const u64*>(&wb[(kk << 7) + ch0]);
                float w0, w1; unpack2(wp, w0, w1);
                u64 w00 = pack2(w0, w0), w11 = pack2(w1, w1);
                a1[0][0] = fma2(hp0, w00, a1[0][0]);
                a1[1][0] = fma2(hp1, w00, a1[1][0]);
                a1[2][0] = fma2(hp2, w00, a1[2][0]);
                a1[3][0] = fma2(hp3, w00, a1[3][0]);
                a1[0][1] = fma2(hp0, w11, a1[0][1]);
                a1[1][1] = fma2(hp1, w11, a1[1][1]);
                a1[2][1] = fma2(hp2, w11, a1[2][1]);
                a1[3][1] = fma2(hp3, w11, a1[3][1]);
            }
            CPA_WAIT();
            __syncthreads();
            pb ^= 1;
        }
        #pragma unroll
        for (int rp = 0; rp < 4; rp++)
            #pragma unroll
            for (int d = 0; d < 2; d++){
                float v0, v1; unpack2(a1[rp][d], v0, v1);
                *reinterpret_cast<u64*>(&m1buf[(ch0+d)*RSTR + r0 + (rp<<1)]) =
                    pack2(fmaxf(v0, 0.f), fmaxf(v1, 0.f));
            }
        __syncthreads();

        // ================= m2 = relu(m1 @ W2 + b2): 2 chunks =================
        u64 a2[4][2];
        {
            float q0, q1; unpack2(cb2r, q0, q1);
            u64 p0 = pack2(q0,q0), p1 = pack2(q1,q1);
            #pragma unroll
            for (int rp = 0; rp < 4; rp++){ a2[rp][0] = p0; a2[rp][1] = p1; }
        }
        for (int c = 0; c < 2; ++c){
            if (c == 0) stage(wsm + ((pb ^ 1) << 13), W2 + WCH, WCH, tid);
            else        stage(wsm + ((pb ^ 1) << 13), Wh, WCH, tid);  // next step chunk 0

            const float* wb = wsm + (pb << 13);
            const int k0 = c << 6;
            #pragma unroll 8
            for (int kk = 0; kk < 64; kk++){
                const u64* h64 = reinterpret_cast<const u64*>(m1buf + (k0 + kk) * RSTR + r0);
                ulonglong2 ha = *reinterpret_cast<const ulonglong2*>(h64);
                ulonglong2 hb = *reinterpret_cast<const ulonglong2*>(h64 + 2);
                u64 hp0 = ha.x, hp1 = ha.y, hp2 = hb.x, hp3 = hb.y;
                u64 wp = *reinterpret_cast<const u64*>(&wb[(kk << 7) + ch0]);
                float w0, w1; unpack2(wp, w0, w1);
                u64 w00 = pack2(w0, w0), w11 = pack2(w1, w1);
                a2[0][0] = fma2(hp0, w00, a2[0][0]);
                a2[1][0] = fma2(hp1, w00, a2[1][0]);
                a2[2][0] = fma2(hp2, w00, a2[2][0]);
                a2[3][0] = fma2(hp3, w00, a2[3][0]);
                a2[0][1] = fma2(hp0, w11, a2[0][1]);
                a2[1][1] = fma2(hp1, w11, a2[1][1]);
                a2[2][1] = fma2(hp2, w11, a2[2][1]);
                a2[3][1] = fma2(hp3, w11, a2[3][1]);
            }
            CPA_WAIT();
            __syncthreads();
            pb ^= 1;
        }

        // ---- out-projection in registers + warp shuffle reduce ----
        float p[8];
        #pragma unroll
        for (int rp = 0; rp < 4; rp++){
            float v0a, v0b, v1a, v1b;
            unpack2(a2[rp][0], v0a, v0b);
            unpack2(a2[rp][1], v1a, v1b);
            p[(rp<<1)  ] = fmaxf(v0a, 0.f) * wo0 + fmaxf(v1a, 0.f) * wo1;
            p[(rp<<1)+1] = fmaxf(v0b, 0.f) * wo0 + fmaxf(v1b, 0.f) * wo1;
        }
        #pragma unroll
        for (int j = 0; j < 8; j++)
            #pragma unroll
            for (int off = 16; off; off >>= 1)
                p[j] += __shfl_xor_sync(0xffffffffu, p[j], off);
        if ((tid & 31) == 0){
            int half = (tid >> 5) & 1;
            #pragma unroll
            for (int j = 0; j < 8; j++) red[half * BT + r0 + j] = p[j];
        }
        __syncthreads();
        if (tid < BT){
            float s = boutv + red[tid] + red[BT + tid];
            predb[tid] = s;
            out[(b0 + tid) * T_STEPS + t] = s;
        }
        __syncthreads();
    }
}

extern "C" void kernel_launch(void* const* d_in, const int* in_sizes, int n_in,
                              void* d_out, int out_size)
{
    (void)in_sizes; (void)n_in; (void)out_size;
    cudaFuncSetAttribute(fused_lstm_kernel, cudaFuncAttributeMaxDynamicSharedMemorySize, SMEM_BYTES);
    int grid = B_TOT / BT; // 256 blocks, 2 per SM on 128 SMs
    fused_lstm_kernel<<<grid, NT, SMEM_BYTES>>>(
        (const float*)d_in[8],  (const float*)d_in[9],  (const float*)d_in[10],
        (const float*)d_in[11], (const float*)d_in[12], (const float*)d_in[13],
        (const float*)d_in[14], (const float*)d_in[15],
        (const float*)d_in[16], (const float*)d_in[17], (const float*)d_in[18],
        (const float*)d_in[19], (const float*)d_in[20], (const float*)d_in[21],
        (const float*)d_in[22], (const float*)d_in[23], (const float*)d_in[24],
        (float*)d_out);
}